// round 4
// baseline (speedup 1.0000x reference)
#include <cuda_runtime.h>

#define BB   8
#define HH   384
#define WW   384
#define HW   (HH * WW)
#define CIN  8
#define OCH  18

typedef unsigned long long ull;

__device__ __forceinline__ ull pk2(float lo, float hi) {
    ull r; asm("mov.b64 %0, {%1, %2};" : "=l"(r) : "f"(lo), "f"(hi)); return r;
}
__device__ __forceinline__ ull f2fma(ull a, ull b, ull c) {
    ull d; asm("fma.rn.f32x2 %0, %1, %2, %3;" : "=l"(d) : "l"(a), "l"(b), "l"(c)); return d;
}
__device__ __forceinline__ float2 upk2(ull v) {
    float2 f; asm("mov.b64 {%0, %1}, %2;" : "=f"(f.x), "=f"(f.y) : "l"(v)); return f;
}

// 85 MB offset scratch: [b][18][H][W]
__device__ float g_off[BB * OCH * HW];

// ================= K1: offset conv (8 -> 18 ch, 3x3, pad 1) =================
// block (32,8); tile 128 x 8; each thread 4 consecutive px (two f2fma pairs).
#define T1W  128
#define T1H  8
#define S1W  132           // 130 used (+2 halo), padded to 132 for 16B rows
#define S1H  10

#define OFF_X1   0
#define SZ_X1    (CIN * S1H * S1W * 4)        // 42240
#define OFF_W1   (OFF_X1 + SZ_X1)             // 42240 (16B aligned)
#define SZ_W1    (CIN * 9 * OCH * 8)          // 10368
#define OFF_B1   (OFF_W1 + SZ_W1)
#define SZ_B1    (OCH * 4)
#define SMEM_K1  (OFF_B1 + SZ_B1)             // 52680

__global__ __launch_bounds__(256, 2)
void offset_conv_k1(const float* __restrict__ pf,
                    const float* __restrict__ cf,
                    const float* __restrict__ mv,
                    const float* __restrict__ ow,   // (18,8,3,3)
                    const float* __restrict__ ob) { // (18,)
    extern __shared__ char smem[];
    float* s_x  = (float*)(smem + OFF_X1);    // [CIN][S1H][S1W]
    ull*   s_w2 = (ull*)  (smem + OFF_W1);    // [(ci*3+ky)*3+kx][o] splat {w,w}
    float* s_b  = (float*)(smem + OFF_B1);

    const int tx  = threadIdx.x;              // 0..31  (x within row)
    const int ty  = threadIdx.y;              // 0..7
    const int tid = ty * 32 + tx;
    const int b   = blockIdx.z;
    const int h0  = blockIdx.y * T1H;
    const int w0  = blockIdx.x * T1W;

    // stage weights (o fastest, splatted)
    for (int i = tid; i < CIN * 9 * OCH; i += 256) {
        int o = i % OCH;
        int t = i / OCH;
        int kx = t % 3; t /= 3;
        int ky = t % 3;
        int ci = t / 3;
        float w = __ldg(ow + ((o * CIN + ci) * 3 + ky) * 3 + kx);
        s_w2[i] = pk2(w, w);
    }
    if (tid < OCH) s_b[tid] = __ldg(ob + tid);

    // stage input tile (8 ch, halo 1, row padded to 132)
    for (int i = tid; i < CIN * S1H * S1W; i += 256) {
        int c  = i % S1W;
        int r  = (i / S1W) % S1H;
        int ch = i / (S1W * S1H);
        int gh = h0 - 1 + r;
        int gw = w0 - 1 + c;
        float v = 0.f;
        if (c < 130 && (unsigned)gh < (unsigned)HH && (unsigned)gw < (unsigned)WW) {
            const float* src;
            if (ch < 3)      src = pf + (((long)b * 3 + ch)     * HH + gh) * WW + gw;
            else if (ch < 6) src = cf + (((long)b * 3 + ch - 3) * HH + gh) * WW + gw;
            else             src = mv + (((long)b * 2 + ch - 6) * HH + gh) * WW + gw;
            v = __ldg(src);
        }
        s_x[i] = v;
    }
    __syncthreads();

    ull accA[OCH], accB[OCH];
#pragma unroll
    for (int o = 0; o < OCH; ++o) {
        float bv = s_b[o];
        accA[o] = pk2(bv, bv);
        accB[o] = accA[o];
    }

#pragma unroll
    for (int ci = 0; ci < CIN; ++ci) {
#pragma unroll
        for (int ky = 0; ky < 3; ++ky) {
            const float* rp = s_x + (ci * S1H + (ty + ky)) * S1W + 4 * tx;
            float4 q  = *reinterpret_cast<const float4*>(rp);      // px-1..px+2
            float2 r2 = *reinterpret_cast<const float2*>(rp + 4);  // px+3, px+4
            ull u01 = pk2(q.x, q.y);
            ull u12 = pk2(q.y, q.z);
            ull u23 = pk2(q.z, q.w);
            ull u34 = pk2(q.w, r2.x);
            ull u45 = pk2(r2.x, r2.y);
            const ulonglong2* wb =
                reinterpret_cast<const ulonglong2*>(s_w2 + (ci * 3 + ky) * 3 * OCH);
#pragma unroll
            for (int o2 = 0; o2 < 9; ++o2) {
                ulonglong2 wk0 = wb[o2];          // kx=0, och {2o2, 2o2+1}
                ulonglong2 wk1 = wb[9 + o2];      // kx=1
                ulonglong2 wk2 = wb[18 + o2];     // kx=2
                const int o = 2 * o2;
                accA[o]   = f2fma(u01, wk0.x, accA[o]);
                accB[o]   = f2fma(u23, wk0.x, accB[o]);
                accA[o+1] = f2fma(u01, wk0.y, accA[o+1]);
                accB[o+1] = f2fma(u23, wk0.y, accB[o+1]);
                accA[o]   = f2fma(u12, wk1.x, accA[o]);
                accB[o]   = f2fma(u34, wk1.x, accB[o]);
                accA[o+1] = f2fma(u12, wk1.y, accA[o+1]);
                accB[o+1] = f2fma(u34, wk1.y, accB[o+1]);
                accA[o]   = f2fma(u23, wk2.x, accA[o]);
                accB[o]   = f2fma(u45, wk2.x, accB[o]);
                accA[o+1] = f2fma(u23, wk2.y, accA[o+1]);
                accB[o+1] = f2fma(u45, wk2.y, accB[o+1]);
            }
        }
    }

    const int h  = h0 + ty;
    const int wp = w0 + 4 * tx;
#pragma unroll
    for (int o = 0; o < OCH; ++o) {
        float2 a = upk2(accA[o]);
        float2 c = upk2(accB[o]);
        *reinterpret_cast<float4*>(g_off + ((long)(b * OCH + o) * HH + h) * WW + wp) =
            make_float4(a.x, a.y, c.x, c.y);
    }
}

// ================= K2: deformable sampling + 3x3x9 einsum =================
// block (32,8); 1 px/thread; warp = 32 consecutive x (minimal gather wavefronts)
__global__ __launch_bounds__(256)
void deform_sample_k2(const float* __restrict__ pf,
                      const float* __restrict__ dw,   // (3,3,3,3)
                      float* __restrict__ out) {
    __shared__ float4 s_dw4[27];   // [c*9+k] = {dw0,dw1,dw2,-}

    const int tx  = threadIdx.x;   // 0..31
    const int ty  = threadIdx.y;   // 0..7
    const int tid = ty * 32 + tx;
    const int b   = blockIdx.z;
    const int h   = blockIdx.y * 8 + ty;
    const int w   = blockIdx.x * 32 + tx;

    if (tid < 27)
        s_dw4[tid] = make_float4(__ldg(dw + tid),
                                 __ldg(dw + 27 + tid),
                                 __ldg(dw + 54 + tid), 0.f);
    __syncthreads();

    // prefetch all 18 offsets (coalesced, MLP 18)
    const int pix = h * WW + w;
    float offv[OCH];
#pragma unroll
    for (int o = 0; o < OCH; ++o)
        offv[o] = __ldg(g_off + (long)(b * OCH + o) * HW + pix);

    const float* p0 = pf + (long)b * 3 * HW;
    float a0 = 0.f, a1 = 0.f, a2 = 0.f;

#pragma unroll
    for (int k = 0; k < 9; ++k) {
        const int kyi = k / 3, kxi = k % 3;
        float py = offv[2 * k]     + (float)(kyi + h - 1);
        float px = offv[2 * k + 1] + (float)(kxi + w - 1);

        int y0 = __float2int_rd(py);
        int x0 = __float2int_rd(px);
        float wy = py - (float)y0;
        float wx = px - (float)x0;
        bool y0v = ((unsigned)y0 < (unsigned)HH);
        bool y1v = ((unsigned)(y0 + 1) < (unsigned)HH);
        bool x0v = ((unsigned)x0 < (unsigned)WW);
        bool x1v = ((unsigned)(x0 + 1) < (unsigned)WW);
        float iy = 1.f - wy, ix = 1.f - wx;
        float w00 = iy * ix, w01 = iy * wx, w10 = wy * ix, w11 = wy * wx;
        int i00 = y0 * WW + x0;

#pragma unroll
        for (int c = 0; c < 3; ++c) {
            const float* p = p0 + c * HW;
            float v00 = (y0v && x0v) ? __ldg(p + i00)          : 0.f;
            float v01 = (y0v && x1v) ? __ldg(p + i00 + 1)      : 0.f;
            float v10 = (y1v && x0v) ? __ldg(p + i00 + WW)     : 0.f;
            float v11 = (y1v && x1v) ? __ldg(p + i00 + WW + 1) : 0.f;
            float s = fmaf(w00, v00, fmaf(w01, v01, fmaf(w10, v10, w11 * v11)));
            float4 d = s_dw4[c * 9 + k];
            a0 = fmaf(d.x, s, a0);
            a1 = fmaf(d.y, s, a1);
            a2 = fmaf(d.z, s, a2);
        }
    }

    out[((long)(b * 3 + 0) * HH + h) * WW + w] = a0;
    out[((long)(b * 3 + 1) * HH + h) * WW + w] = a1;
    out[((long)(b * 3 + 2) * HH + h) * WW + w] = a2;
}

extern "C" void kernel_launch(void* const* d_in, const int* in_sizes, int n_in,
                              void* d_out, int out_size) {
    const float* pf = (const float*)d_in[0];
    const float* cf = (const float*)d_in[1];
    const float* mv = (const float*)d_in[2];
    const float* ow = (const float*)d_in[3];
    const float* ob = (const float*)d_in[4];
    const float* dw = (const float*)d_in[5];
    float* out = (float*)d_out;

    cudaFuncSetAttribute(offset_conv_k1,
                         cudaFuncAttributeMaxDynamicSharedMemorySize, SMEM_K1);

    dim3 blk1(32, 8);
    dim3 grd1(WW / T1W, HH / T1H, BB);    // 3 x 48 x 8 = 1152
    offset_conv_k1<<<grd1, blk1, SMEM_K1>>>(pf, cf, mv, ow, ob);

    dim3 blk2(32, 8);
    dim3 grd2(WW / 32, HH / 8, BB);       // 12 x 48 x 8 = 4608
    deform_sample_k2<<<grd2, blk2>>>(pf, dw, out);
}

// round 5
// speedup vs baseline: 1.0386x; 1.0386x over previous
#include <cuda_runtime.h>

#define BB   8
#define HH   384
#define WW   384
#define HW   (HH * WW)
#define CIN  8
#define OCH  18

typedef unsigned long long ull;

__device__ __forceinline__ ull pk2(float lo, float hi) {
    ull r; asm("mov.b64 %0, {%1, %2};" : "=l"(r) : "f"(lo), "f"(hi)); return r;
}
__device__ __forceinline__ ull f2fma(ull a, ull b, ull c) {
    ull d; asm("fma.rn.f32x2 %0, %1, %2, %3;" : "=l"(d) : "l"(a), "l"(b), "l"(c)); return d;
}
__device__ __forceinline__ float2 upk2(ull v) {
    float2 f; asm("mov.b64 {%0, %1}, %2;" : "=f"(f.x), "=f"(f.y) : "l"(v)); return f;
}

// 85 MB offset scratch: [b][18][H][W]
__device__ float g_off[BB * OCH * HW];

// ================= K1: offset conv (8 -> 18 ch, 3x3, pad 1) =================
// block (16,8) = 128 thr; tile 64 x 8; 4 px/thread; TWO channel passes (10+8)
#define T1W  64
#define T1H  8
#define S1W  68            // 66 used (64 + 2 halo), padded to 68 (16B rows)
#define S1H  10

#define OFF_X1   0
#define SZ_X1    (CIN * S1H * S1W * 4)        // 21760
#define OFF_W1   (OFF_X1 + SZ_X1)             // 21760 (16B aligned)
#define SZ_W1    (CIN * 9 * OCH * 8)          // 10368
#define OFF_B1   (OFF_W1 + SZ_W1)             // 32128
#define SZ_B1    (OCH * 4)                    // 72
#define SMEM_K1  (OFF_B1 + SZ_B1)             // 32200

// One pass over output-channel pairs [J0, J0+NJ).
template<int J0, int NJ>
__device__ __forceinline__ void conv_pass(const float* __restrict__ s_x,
                                          const ulonglong2* __restrict__ s_wp, // [(ci*3+ky)*3+kx][9 pairs]
                                          const float* __restrict__ s_b,
                                          int tx, int ty, int b, int h, int wp) {
    ull accA[2 * NJ], accB[2 * NJ];
#pragma unroll
    for (int j = 0; j < NJ; ++j) {
        float b0 = s_b[2 * (J0 + j)];
        float b1 = s_b[2 * (J0 + j) + 1];
        accA[2 * j]     = pk2(b0, b0);  accB[2 * j]     = accA[2 * j];
        accA[2 * j + 1] = pk2(b1, b1);  accB[2 * j + 1] = accA[2 * j + 1];
    }

#pragma unroll 2
    for (int ci = 0; ci < CIN; ++ci) {
#pragma unroll
        for (int ky = 0; ky < 3; ++ky) {
            const float* rp = s_x + (ci * S1H + (ty + ky)) * S1W + 4 * tx;
            float4 q  = *reinterpret_cast<const float4*>(rp);      // px-1..px+2
            float2 r2 = *reinterpret_cast<const float2*>(rp + 4);  // px+3, px+4
            ull u01 = pk2(q.x, q.y);
            ull u12 = pk2(q.y, q.z);
            ull u23 = pk2(q.z, q.w);
            ull u34 = pk2(q.w, r2.x);
            ull u45 = pk2(r2.x, r2.y);
            const ulonglong2* wb = s_wp + (ci * 3 + ky) * 27;      // kx stride = 9 pairs
#pragma unroll
            for (int j = 0; j < NJ; ++j) {
                ulonglong2 w0 = wb[J0 + j];        // kx=0, och {2(J0+j), +1}
                ulonglong2 w1 = wb[9 + J0 + j];    // kx=1
                ulonglong2 w2 = wb[18 + J0 + j];   // kx=2
                const int a = 2 * j;
                accA[a]   = f2fma(u01, w0.x, accA[a]);
                accB[a]   = f2fma(u23, w0.x, accB[a]);
                accA[a+1] = f2fma(u01, w0.y, accA[a+1]);
                accB[a+1] = f2fma(u23, w0.y, accB[a+1]);
                accA[a]   = f2fma(u12, w1.x, accA[a]);
                accB[a]   = f2fma(u34, w1.x, accB[a]);
                accA[a+1] = f2fma(u12, w1.y, accA[a+1]);
                accB[a+1] = f2fma(u34, w1.y, accB[a+1]);
                accA[a]   = f2fma(u23, w2.x, accA[a]);
                accB[a]   = f2fma(u45, w2.x, accB[a]);
                accA[a+1] = f2fma(u23, w2.y, accA[a+1]);
                accB[a+1] = f2fma(u45, w2.y, accB[a+1]);
            }
        }
    }

#pragma unroll
    for (int j = 0; j < NJ; ++j) {
#pragma unroll
        for (int s = 0; s < 2; ++s) {
            int o = 2 * (J0 + j) + s;
            float2 a = upk2(accA[2 * j + s]);
            float2 c = upk2(accB[2 * j + s]);
            *reinterpret_cast<float4*>(g_off + ((long)(b * OCH + o) * HH + h) * WW + wp) =
                make_float4(a.x, a.y, c.x, c.y);
        }
    }
}

__global__ __launch_bounds__(128, 5)
void offset_conv_k1(const float* __restrict__ pf,
                    const float* __restrict__ cf,
                    const float* __restrict__ mv,
                    const float* __restrict__ ow,   // (18,8,3,3)
                    const float* __restrict__ ob) { // (18,)
    extern __shared__ char smem[];
    float* s_x  = (float*)(smem + OFF_X1);    // [CIN][S1H][S1W]
    ull*   s_w2 = (ull*)  (smem + OFF_W1);    // [(ci*3+ky)*3+kx][o] splat {w,w}
    float* s_b  = (float*)(smem + OFF_B1);

    const int tx  = threadIdx.x;              // 0..15
    const int ty  = threadIdx.y;              // 0..7
    const int tid = ty * 16 + tx;
    const int b   = blockIdx.z;
    const int h0  = blockIdx.y * T1H;
    const int w0  = blockIdx.x * T1W;

    // stage weights (o fastest, splatted)
    for (int i = tid; i < CIN * 9 * OCH; i += 128) {
        int o = i % OCH;
        int t = i / OCH;
        int kx = t % 3; t /= 3;
        int ky = t % 3;
        int ci = t / 3;
        float w = __ldg(ow + ((o * CIN + ci) * 3 + ky) * 3 + kx);
        s_w2[i] = pk2(w, w);
    }
    if (tid < OCH) s_b[tid] = __ldg(ob + tid);

    // stage input tile (8 ch, halo 1, rows padded to 68)
    for (int i = tid; i < CIN * S1H * S1W; i += 128) {
        int c  = i % S1W;
        int r  = (i / S1W) % S1H;
        int ch = i / (S1W * S1H);
        int gh = h0 - 1 + r;
        int gw = w0 - 1 + c;
        float v = 0.f;
        if (c < 66 && (unsigned)gh < (unsigned)HH && (unsigned)gw < (unsigned)WW) {
            const float* src;
            if (ch < 3)      src = pf + (((long)b * 3 + ch)     * HH + gh) * WW + gw;
            else if (ch < 6) src = cf + (((long)b * 3 + ch - 3) * HH + gh) * WW + gw;
            else             src = mv + (((long)b * 2 + ch - 6) * HH + gh) * WW + gw;
            v = __ldg(src);
        }
        s_x[i] = v;
    }
    __syncthreads();

    const int h  = h0 + ty;
    const int wp = w0 + 4 * tx;
    const ulonglong2* s_wp = reinterpret_cast<const ulonglong2*>(s_w2);

    conv_pass<0, 5>(s_x, s_wp, s_b, tx, ty, b, h, wp);   // och 0..9
    conv_pass<5, 4>(s_x, s_wp, s_b, tx, ty, b, h, wp);   // och 10..17
}

// ================= K2: deformable sampling + 3x3x9 einsum =================
// block (32,8); 1 px/thread; warp = 32 consecutive x (minimal gather wavefronts)
__global__ __launch_bounds__(256)
void deform_sample_k2(const float* __restrict__ pf,
                      const float* __restrict__ dw,   // (3,3,3,3)
                      float* __restrict__ out) {
    __shared__ float4 s_dw4[27];   // [c*9+k] = {dw0,dw1,dw2,-}

    const int tx  = threadIdx.x;   // 0..31
    const int ty  = threadIdx.y;   // 0..7
    const int tid = ty * 32 + tx;
    const int b   = blockIdx.z;
    const int h   = blockIdx.y * 8 + ty;
    const int w   = blockIdx.x * 32 + tx;

    if (tid < 27)
        s_dw4[tid] = make_float4(__ldg(dw + tid),
                                 __ldg(dw + 27 + tid),
                                 __ldg(dw + 54 + tid), 0.f);
    __syncthreads();

    // prefetch all 18 offsets (coalesced, MLP 18)
    const int pix = h * WW + w;
    float offv[OCH];
#pragma unroll
    for (int o = 0; o < OCH; ++o)
        offv[o] = __ldg(g_off + (long)(b * OCH + o) * HW + pix);

    const float* p0 = pf + (long)b * 3 * HW;
    float a0 = 0.f, a1 = 0.f, a2 = 0.f;

#pragma unroll
    for (int k = 0; k < 9; ++k) {
        const int kyi = k / 3, kxi = k % 3;
        float py = offv[2 * k]     + (float)(kyi + h - 1);
        float px = offv[2 * k + 1] + (float)(kxi + w - 1);

        int y0 = __float2int_rd(py);
        int x0 = __float2int_rd(px);
        float wy = py - (float)y0;
        float wx = px - (float)x0;
        bool y0v = ((unsigned)y0 < (unsigned)HH);
        bool y1v = ((unsigned)(y0 + 1) < (unsigned)HH);
        bool x0v = ((unsigned)x0 < (unsigned)WW);
        bool x1v = ((unsigned)(x0 + 1) < (unsigned)WW);
        float iy = 1.f - wy, ix = 1.f - wx;
        float w00 = iy * ix, w01 = iy * wx, w10 = wy * ix, w11 = wy * wx;
        int i00 = y0 * WW + x0;

#pragma unroll
        for (int c = 0; c < 3; ++c) {
            const float* p = p0 + c * HW;
            float v00 = (y0v && x0v) ? __ldg(p + i00)          : 0.f;
            float v01 = (y0v && x1v) ? __ldg(p + i00 + 1)      : 0.f;
            float v10 = (y1v && x0v) ? __ldg(p + i00 + WW)     : 0.f;
            float v11 = (y1v && x1v) ? __ldg(p + i00 + WW + 1) : 0.f;
            float s = fmaf(w00, v00, fmaf(w01, v01, fmaf(w10, v10, w11 * v11)));
            float4 d = s_dw4[c * 9 + k];
            a0 = fmaf(d.x, s, a0);
            a1 = fmaf(d.y, s, a1);
            a2 = fmaf(d.z, s, a2);
        }
    }

    out[((long)(b * 3 + 0) * HH + h) * WW + w] = a0;
    out[((long)(b * 3 + 1) * HH + h) * WW + w] = a1;
    out[((long)(b * 3 + 2) * HH + h) * WW + w] = a2;
}

extern "C" void kernel_launch(void* const* d_in, const int* in_sizes, int n_in,
                              void* d_out, int out_size) {
    const float* pf = (const float*)d_in[0];
    const float* cf = (const float*)d_in[1];
    const float* mv = (const float*)d_in[2];
    const float* ow = (const float*)d_in[3];
    const float* ob = (const float*)d_in[4];
    const float* dw = (const float*)d_in[5];
    float* out = (float*)d_out;

    cudaFuncSetAttribute(offset_conv_k1,
                         cudaFuncAttributeMaxDynamicSharedMemorySize, SMEM_K1);

    dim3 blk1(16, 8);
    dim3 grd1(WW / T1W, HH / T1H, BB);    // 6 x 48 x 8 = 2304
    offset_conv_k1<<<grd1, blk1, SMEM_K1>>>(pf, cf, mv, ow, ob);

    dim3 blk2(32, 8);
    dim3 grd2(WW / 32, HH / 8, BB);       // 12 x 48 x 8 = 4608
    deform_sample_k2<<<grd2, blk2>>>(pf, dw, out);
}